// round 16
// baseline (speedup 1.0000x reference)
#include <cuda_runtime.h>
#include <cstdint>
#include <cstddef>

#define NB   32
#define NFR  16
#define NT   192
#define DD   256
#define NS   21
#define BSROWS (NB*NS)          // 672
#define SM_SCALE 0.0625f
#define ATT_EPS 1e-8f
#define LN_EPS  1e-5f
#define GRID 148
#define NTHR 256

// ---------------- scratch (device globals; no allocation) ----------------
static __device__ float g_k[(size_t)NB*NFR*NT*DD];
static __device__ float g_v[(size_t)NB*NFR*NT*DD];
static __device__ float g_slots[BSROWS*DD];
static __device__ float g_q[BSROWS*DD];
static __device__ float g_upd[BSROWS*DD];
static __device__ float g_gh[(size_t)BSROWS*3*DD];
static __device__ float g_h[BSROWS*DD];
static __device__ float g_t[BSROWS*DD];

static __device__ unsigned g_cnt = 0;
static __device__ volatile unsigned g_gen = 0;

// ---------------- software grid barrier (R10-proven) ----------------------
__device__ __forceinline__ void gsync() {
    __syncthreads();
    if (threadIdx.x == 0) {
        __threadfence();
        unsigned gen = g_gen;
        if (atomicAdd(&g_cnt, 1u) == GRID - 1u) {
            g_cnt = 0;
            __threadfence();
            g_gen = gen + 1u;
        } else {
            while (g_gen == gen) { __nanosleep(64); }
        }
        __threadfence();
    }
    __syncthreads();
}

// ---------------- shared memory union -------------------------------------
struct GemmSm {
    float As[2][32][36];    // double-buffered A^T: [buf][k][row]
    float Ws[2][32][68];    // double-buffered W^T: [buf][k][col]
    float mean[32], rstd[32];
    float red[32][8][2];
    float dt[NS][66];
};
struct UpdSm {
    float a_s[NS*NT];
    float rsum[NS];
    float red[4][NS][64];
};
union SmemAll {
    GemmSm g;
    UpdSm  u;
};

// ---------------- LN stats for 32 rows at Arow -> s.mean/s.rstd -----------
__device__ void ln_stats(GemmSm& s, const float* __restrict__ Arow)
{
    const int tid = threadIdx.x;
    int r = tid >> 3, p = tid & 7;
    const float4* ap = reinterpret_cast<const float4*>(Arow + r * DD + p * 32);
    float ss = 0.f, ss2 = 0.f;
    #pragma unroll
    for (int u = 0; u < 8; ++u) {
        float4 x = ap[u];
        ss  += x.x + x.y + x.z + x.w;
        ss2 += x.x*x.x + x.y*x.y + x.z*x.z + x.w*x.w;
    }
    s.red[r][p][0] = ss; s.red[r][p][1] = ss2;
    __syncthreads();
    if (tid < 32) {
        float a0 = 0.f, a1 = 0.f;
        #pragma unroll
        for (int q = 0; q < 8; ++q) { a0 += s.red[tid][q][0]; a1 += s.red[tid][q][1]; }
        float m = a0 * (1.0f/DD);
        s.mean[tid] = m;
        s.rstd[tid] = rsqrtf(a1*(1.0f/DD) - m*m + LN_EPS);
    }
    __syncthreads();
}

// ---------------- pipelined 32x64 GEMM core, K=256 ------------------------
// acc[4][2]: rows 4*(tid>>5)+0..3, cols 2*(tid&31)+0..1 of (LN?(A)) @ W^T.
template<bool LN>
__device__ void mm_core(GemmSm& s,
                        const float* __restrict__ Arow,   // A + row0*256
                        const float* __restrict__ Wcol,   // W + col0*256
                        const float* __restrict__ gamma,
                        const float* __restrict__ beta,
                        float (&acc)[4][2])
{
    const int tid = threadIdx.x;
    const int ar = tid >> 3;            // 0..31 (A row / W col pair base)
    const int ak = (tid & 7) << 2;      // k-quad 0,4,..,28
    const float* aP  = Arow + (size_t)ar * DD + ak;
    const float* w0P = Wcol + (size_t)ar * DD + ak;
    const float* w1P = Wcol + (size_t)(ar + 32) * DD + ak;

    float4 aF  = *reinterpret_cast<const float4*>(aP);
    float4 w0F = *reinterpret_cast<const float4*>(w0P);
    float4 w1F = *reinterpret_cast<const float4*>(w1P);
    if (LN) {
        float m = s.mean[ar], rs = s.rstd[ar];
        float4 gg = *reinterpret_cast<const float4*>(gamma + ak);
        float4 bb = *reinterpret_cast<const float4*>(beta  + ak);
        aF.x = (aF.x - m)*rs*gg.x + bb.x;
        aF.y = (aF.y - m)*rs*gg.y + bb.y;
        aF.z = (aF.z - m)*rs*gg.z + bb.z;
        aF.w = (aF.w - m)*rs*gg.w + bb.w;
    }
    s.As[0][ak+0][ar]=aF.x; s.As[0][ak+1][ar]=aF.y; s.As[0][ak+2][ar]=aF.z; s.As[0][ak+3][ar]=aF.w;
    s.Ws[0][ak+0][ar]=w0F.x; s.Ws[0][ak+1][ar]=w0F.y; s.Ws[0][ak+2][ar]=w0F.z; s.Ws[0][ak+3][ar]=w0F.w;
    s.Ws[0][ak+0][ar+32]=w1F.x; s.Ws[0][ak+1][ar+32]=w1F.y; s.Ws[0][ak+2][ar+32]=w1F.z; s.Ws[0][ak+3][ar+32]=w1F.w;
    __syncthreads();

    const int ty = tid >> 5;
    const int tx = tid & 31;

    #pragma unroll
    for (int kk = 0; kk < 8; ++kk) {
        const int cur = kk & 1, nxt = cur ^ 1;
        if (kk < 7) {
            const int ko = (kk + 1) << 5;
            aF  = *reinterpret_cast<const float4*>(aP  + ko);
            w0F = *reinterpret_cast<const float4*>(w0P + ko);
            w1F = *reinterpret_cast<const float4*>(w1P + ko);
            if (LN) {
                float m = s.mean[ar], rs = s.rstd[ar];
                float4 gg = *reinterpret_cast<const float4*>(gamma + ko + ak);
                float4 bb = *reinterpret_cast<const float4*>(beta  + ko + ak);
                aF.x = (aF.x - m)*rs*gg.x + bb.x;
                aF.y = (aF.y - m)*rs*gg.y + bb.y;
                aF.z = (aF.z - m)*rs*gg.z + bb.z;
                aF.w = (aF.w - m)*rs*gg.w + bb.w;
            }
        }
        #pragma unroll
        for (int k = 0; k < 32; ++k) {
            float4 a = *reinterpret_cast<const float4*>(&s.As[cur][k][ty<<2]);
            float2 b = *reinterpret_cast<const float2*>(&s.Ws[cur][k][tx<<1]);
            acc[0][0]+=a.x*b.x; acc[0][1]+=a.x*b.y;
            acc[1][0]+=a.y*b.x; acc[1][1]+=a.y*b.y;
            acc[2][0]+=a.z*b.x; acc[2][1]+=a.z*b.y;
            acc[3][0]+=a.w*b.x; acc[3][1]+=a.w*b.y;
        }
        if (kk < 7) {
            s.As[nxt][ak+0][ar]=aF.x; s.As[nxt][ak+1][ar]=aF.y; s.As[nxt][ak+2][ar]=aF.z; s.As[nxt][ak+3][ar]=aF.w;
            s.Ws[nxt][ak+0][ar]=w0F.x; s.Ws[nxt][ak+1][ar]=w0F.y; s.Ws[nxt][ak+2][ar]=w0F.z; s.Ws[nxt][ak+3][ar]=w0F.w;
            s.Ws[nxt][ak+0][ar+32]=w1F.x; s.Ws[nxt][ak+1][ar+32]=w1F.y; s.Ws[nxt][ak+2][ar+32]=w1F.z; s.Ws[nxt][ak+3][ar+32]=w1F.w;
        }
        __syncthreads();
    }
}

// ---------------- P1 items -------------------------------------------------
__device__ void q_item(GemmSm& s, int t,
                       const float* __restrict__ Wq, const float* __restrict__ bq,
                       const float* __restrict__ gsl, const float* __restrict__ besl)
{
    int rb = t >> 2, cb = t & 3;
    const float* Arow = g_slots + (size_t)rb * 32 * DD;
    ln_stats(s, Arow);
    float acc[4][2] = {};
    mm_core<true>(s, Arow, Wq + (size_t)cb * 64 * DD, gsl, besl, acc);
    const int ty = threadIdx.x >> 5, tx = threadIdx.x & 31;
    int col = cb*64 + (tx<<1);
    float2 bb = *reinterpret_cast<const float2*>(bq + col);
    #pragma unroll
    for (int ii = 0; ii < 4; ++ii) {
        int r = rb*32 + (ty<<2) + ii;
        float2 o; o.x = acc[ii][0] + bb.x; o.y = acc[ii][1] + bb.y;
        *reinterpret_cast<float2*>(g_q + (size_t)r * DD + col) = o;
    }
}

__device__ void gh_item(GemmSm& s, int t,
                        const float* __restrict__ W_hh, const float* __restrict__ b_hh)
{
    int rb = t >> 2, db = t & 3;
    const float* Arow = g_slots + (size_t)rb * 32 * DD;
    float acc[3][4][2] = {};
    #pragma unroll 1
    for (int g = 0; g < 3; ++g)
        mm_core<false>(s, Arow, W_hh + (size_t)(g*256 + db*64) * DD, nullptr, nullptr, acc[g]);
    const int ty = threadIdx.x >> 5, tx = threadIdx.x & 31;
    #pragma unroll
    for (int g = 0; g < 3; ++g) {
        int col = g*256 + db*64 + (tx<<1);
        float2 bb = *reinterpret_cast<const float2*>(b_hh + col);
        #pragma unroll
        for (int ii = 0; ii < 4; ++ii) {
            int r = rb*32 + (ty<<2) + ii;
            float2 o; o.x = acc[g][ii][0] + bb.x; o.y = acc[g][ii][1] + bb.y;
            *reinterpret_cast<float2*>(g_gh + (size_t)r * 3*DD + col) = o;
        }
    }
}

// ---------------- P4: gi (3 gates, in-reg) + GRU -> h ---------------------
__device__ void gru_item(GemmSm& s, int t,
                         const float* __restrict__ W_ih, const float* __restrict__ b_ih)
{
    int rb = t >> 2, db = t & 3;
    const float* Arow = g_upd + (size_t)rb * 32 * DD;
    float acc[3][4][2] = {};
    #pragma unroll 1
    for (int g = 0; g < 3; ++g)
        mm_core<false>(s, Arow, W_ih + (size_t)(g*256 + db*64) * DD, nullptr, nullptr, acc[g]);
    const int ty = threadIdx.x >> 5, tx = threadIdx.x & 31;
    int d = db*64 + (tx<<1);
    float2 br = *reinterpret_cast<const float2*>(b_ih + d);
    float2 bz = *reinterpret_cast<const float2*>(b_ih + 256 + d);
    float2 bn = *reinterpret_cast<const float2*>(b_ih + 512 + d);
    #pragma unroll
    for (int ii = 0; ii < 4; ++ii) {
        int r = rb*32 + (ty<<2) + ii;
        size_t gb = (size_t)r * 3*DD + d;
        float2 hr = *reinterpret_cast<const float2*>(g_gh + gb);
        float2 hz = *reinterpret_cast<const float2*>(g_gh + gb + 256);
        float2 hn = *reinterpret_cast<const float2*>(g_gh + gb + 512);
        float2 hv = *reinterpret_cast<const float2*>(g_slots + (size_t)r * DD + d);
        float irx = acc[0][ii][0] + br.x, iry = acc[0][ii][1] + br.y;
        float izx = acc[1][ii][0] + bz.x, izy = acc[1][ii][1] + bz.y;
        float inx = acc[2][ii][0] + bn.x, iny = acc[2][ii][1] + bn.y;
        float2 o;
        {
            float rr = 1.0f/(1.0f+__expf(-(irx + hr.x)));
            float zz = 1.0f/(1.0f+__expf(-(izx + hz.x)));
            float nn = tanhf(inx + rr*hn.x);
            o.x = (1.0f - zz)*nn + zz*hv.x;
        }
        {
            float rr = 1.0f/(1.0f+__expf(-(iry + hr.y)));
            float zz = 1.0f/(1.0f+__expf(-(izy + hz.y)));
            float nn = tanhf(iny + rr*hn.y);
            o.y = (1.0f - zz)*nn + zz*hv.y;
        }
        *reinterpret_cast<float2*>(g_h + (size_t)r * DD + d) = o;
    }
}

// ---------------- P5/P6: MLP tiles -----------------------------------------
__device__ void mlp1_item(GemmSm& s, int t,
                          const float* __restrict__ W1, const float* __restrict__ b1,
                          const float* __restrict__ gff, const float* __restrict__ beff)
{
    int rb = t >> 2, cb = t & 3;
    const float* Arow = g_h + (size_t)rb * 32 * DD;
    ln_stats(s, Arow);
    float acc[4][2] = {};
    mm_core<true>(s, Arow, W1 + (size_t)cb * 64 * DD, gff, beff, acc);
    const int ty = threadIdx.x >> 5, tx = threadIdx.x & 31;
    int col = cb*64 + (tx<<1);
    float2 bb = *reinterpret_cast<const float2*>(b1 + col);
    #pragma unroll
    for (int ii = 0; ii < 4; ++ii) {
        int r = rb*32 + (ty<<2) + ii;
        float2 o;
        o.x = fmaxf(acc[ii][0] + bb.x, 0.f);
        o.y = fmaxf(acc[ii][1] + bb.y, 0.f);
        *reinterpret_cast<float2*>(g_t + (size_t)r * DD + col) = o;
    }
}

__device__ void mlp2_item(GemmSm& s, int t,
                          const float* __restrict__ W2, const float* __restrict__ b2)
{
    int rb = t >> 2, cb = t & 3;
    const float* Arow = g_t + (size_t)rb * 32 * DD;
    float acc[4][2] = {};
    mm_core<false>(s, Arow, W2 + (size_t)cb * 64 * DD, nullptr, nullptr, acc);
    const int ty = threadIdx.x >> 5, tx = threadIdx.x & 31;
    int col = cb*64 + (tx<<1);
    float2 bb = *reinterpret_cast<const float2*>(b2 + col);
    #pragma unroll
    for (int ii = 0; ii < 4; ++ii) {
        int r = rb*32 + (ty<<2) + ii;
        float2 hh = *reinterpret_cast<const float2*>(g_h + (size_t)r * DD + col);
        float2 o;
        o.x = acc[ii][0] + bb.x + hh.x;
        o.y = acc[ii][1] + bb.y + hh.y;
        *reinterpret_cast<float2*>(g_slots + (size_t)r * DD + col) = o;
    }
}

// ---------------- attention tile: dots + col-softmax (+eps) ---------------
__device__ void attn_tile(SmemAll* smp,
                          const float* __restrict__ q,
                          const float* __restrict__ kall,
                          float* __restrict__ out_attn,
                          int f, int b, int j0)
{
    GemmSm& s = smp->g;
    const int tid = threadIdx.x;
    const float* Ab = q + (size_t)b * NS * DD;
    const float* Wb = kall + ((size_t)(b*NFR + f) * NT + j0) * DD;
    float acc[4][4] = {};
    const int ty = (tid & 127) >> 4;
    const int tx = tid & 15;

    for (int kk = 0; kk < DD; kk += 32) {
        {
            int i = tid >> 3, kq = (tid & 7) << 2;
            float4 v = make_float4(0.f, 0.f, 0.f, 0.f);
            if (i < NS) v = *reinterpret_cast<const float4*>(Ab + (size_t)i * DD + kk + kq);
            s.As[0][kq+0][i]=v.x; s.As[0][kq+1][i]=v.y; s.As[0][kq+2][i]=v.z; s.As[0][kq+3][i]=v.w;
        }
        #pragma unroll
        for (int l = 0; l < 2; ++l) {
            int t = tid + l * 256;
            int j = t >> 3, kq = (t & 7) << 2;
            float4 v = *reinterpret_cast<const float4*>(Wb + (size_t)j * DD + kk + kq);
            s.Ws[0][kq+0][j]=v.x; s.Ws[0][kq+1][j]=v.y; s.Ws[0][kq+2][j]=v.z; s.Ws[0][kq+3][j]=v.w;
        }
        __syncthreads();
        if (tid < 128) {
            #pragma unroll
            for (int k = 0; k < 32; ++k) {
                float4 a  = *reinterpret_cast<const float4*>(&s.As[0][k][ty<<2]);
                float4 b4 = *reinterpret_cast<const float4*>(&s.Ws[0][k][tx<<2]);
                acc[0][0]+=a.x*b4.x; acc[0][1]+=a.x*b4.y; acc[0][2]+=a.x*b4.z; acc[0][3]+=a.x*b4.w;
                acc[1][0]+=a.y*b4.x; acc[1][1]+=a.y*b4.y; acc[1][2]+=a.y*b4.z; acc[1][3]+=a.y*b4.w;
                acc[2][0]+=a.z*b4.x; acc[2][1]+=a.z*b4.y; acc[2][2]+=a.z*b4.z; acc[2][3]+=a.z*b4.w;
                acc[3][0]+=a.w*b4.x; acc[3][1]+=a.w*b4.y; acc[3][2]+=a.w*b4.z; acc[3][3]+=a.w*b4.w;
            }
        }
        __syncthreads();
    }
    if (tid < 128) {
        #pragma unroll
        for (int ii = 0; ii < 4; ++ii) {
            int i = (ty<<2) + ii;
            if (i < NS) {
                s.dt[i][(tx<<2)+0] = acc[ii][0]*SM_SCALE;
                s.dt[i][(tx<<2)+1] = acc[ii][1]*SM_SCALE;
                s.dt[i][(tx<<2)+2] = acc[ii][2]*SM_SCALE;
                s.dt[i][(tx<<2)+3] = acc[ii][3]*SM_SCALE;
            }
        }
    }
    __syncthreads();
    if (tid < 64) {
        int j = tid;
        float m = -1e30f;
        #pragma unroll
        for (int i = 0; i < NS; ++i) m = fmaxf(m, s.dt[i][j]);
        float e[NS]; float sum = 0.f;
        #pragma unroll
        for (int i = 0; i < NS; ++i) { e[i] = __expf(s.dt[i][j] - m); sum += e[i]; }
        float inv = 1.0f / sum;
        float* op = out_attn + ((size_t)(b*NFR + f) * NS) * NT + j0 + j;
        #pragma unroll
        for (int i = 0; i < NS; ++i) op[(size_t)i * NT] = e[i]*inv + ATT_EPS;
    }
    __syncthreads();
}

// ---------------- updates tile = (attn @ v) / rowsum(attn) ----------------
__device__ void upd_tile(SmemAll* sm,
                         const float* __restrict__ attn,
                         const float* __restrict__ vall,
                         float* __restrict__ upd,
                         int f, int b, int d0)
{
    UpdSm& s = sm->u;
    const int tid = threadIdx.x;
    const float* ab = attn + (size_t)(b*NFR + f) * NS * NT;
    const float4* ab4 = reinterpret_cast<const float4*>(ab);
    float4* as4 = reinterpret_cast<float4*>(s.a_s);
    for (int t = tid; t < NS*NT/4; t += NTHR) as4[t] = ab4[t];
    __syncthreads();
    if (tid < NS) {
        float sum = 0.f;
        const float* row = &s.a_s[tid * NT];
        for (int j = 0; j < NT; ++j) sum += row[j];
        s.rsum[tid] = 1.0f / sum;
    }
    int jg = tid >> 6, dl = tid & 63;
    const float* vb = vall + ((size_t)(b*NFR + f) * NT) * DD + d0 + dl;
    float acc[NS] = {};
    int jbase = jg * 48;
    for (int j4 = 0; j4 < 48; j4 += 4) {
        float v0 = vb[(size_t)(jbase + j4 + 0) * DD];
        float v1 = vb[(size_t)(jbase + j4 + 1) * DD];
        float v2 = vb[(size_t)(jbase + j4 + 2) * DD];
        float v3 = vb[(size_t)(jbase + j4 + 3) * DD];
        #pragma unroll
        for (int i = 0; i < NS; ++i) {
            float4 a = *reinterpret_cast<const float4*>(&s.a_s[i*NT + jbase + j4]);
            acc[i] += a.x*v0 + a.y*v1 + a.z*v2 + a.w*v3;
        }
    }
    #pragma unroll
    for (int i = 0; i < NS; ++i) s.red[jg][i][dl] = acc[i];
    __syncthreads();
    if (tid < 64) {
        #pragma unroll
        for (int i = 0; i < NS; ++i) {
            float sum = s.red[0][i][tid] + s.red[1][i][tid] + s.red[2][i][tid] + s.red[3][i][tid];
            upd[((size_t)b*NS + i) * DD + d0 + tid] = sum * s.rsum[i];
        }
    }
    __syncthreads();
}

// ---------------- persistent serial-core kernel ----------------------------
__global__ void __launch_bounds__(NTHR, 1)
persist_kernel(const float* __restrict__ noise,
               const float* __restrict__ mu,
               const float* __restrict__ sg,
               const float* __restrict__ Wq, const float* __restrict__ bq,
               const float* __restrict__ W1, const float* __restrict__ b1,
               const float* __restrict__ W2, const float* __restrict__ b2,
               const float* __restrict__ W_ih, const float* __restrict__ b_ih,
               const float* __restrict__ W_hh, const float* __restrict__ b_hh,
               const float* __restrict__ gsl, const float* __restrict__ besl,
               const float* __restrict__ gff, const float* __restrict__ beff,
               float* __restrict__ out_slots,
               float* __restrict__ out_attn)
{
    __shared__ SmemAll sm;
    const int tid = threadIdx.x;
    const int bid = blockIdx.x;

    for (int idx = bid*NTHR + tid; idx < BSROWS*DD; idx += GRID*NTHR) {
        int d = idx & (DD - 1);
        g_slots[idx] = mu[d] + sg[d] * noise[idx];
    }
    gsync();

    for (int f = 0; f < NFR; ++f) {
        for (int it = 0; it < 3; ++it) {
            // ---- P1: gh (84 triple items) + q (84 tiles over 64 CTAs) ----
            if (bid < 84) {
                gh_item(sm.g, bid, W_hh, b_hh);
            } else {
                int u = bid - 84;
                if (u < 44) {
                    q_item(sm.g, u, Wq, bq, gsl, besl);
                } else {
                    int v = 44 + ((u - 44) << 1);
                    q_item(sm.g, v,     Wq, bq, gsl, besl);
                    q_item(sm.g, v + 1, Wq, bq, gsl, besl);
                }
            }
            gsync();
            // ---- P2: dots + softmax(+eps) -> out_attn (96 items) ----
            if (bid < 96) {
                int b = bid / 3, j0 = (bid - b*3) * 64;
                attn_tile(&sm, g_q, g_k, out_attn, f, b, j0);
            }
            gsync();
            // ---- P3: updates (128 items) ----
            if (bid < 128) {
                int b = bid >> 2, d0 = (bid & 3) * 64;
                upd_tile(&sm, out_attn, g_v, g_upd, f, b, d0);
            }
            gsync();
            // ---- P4: gi (in-reg, 3 gates) + GRU -> h (84 items) ----
            if (bid < 84) gru_item(sm.g, bid, W_ih, b_ih);
            gsync();
            // ---- P5: t = relu(LN(h)@W1^T + b1) (84 items) ----
            if (bid < 84) mlp1_item(sm.g, bid, W1, b1, gff, beff);
            gsync();
            // ---- P6: slots = h + t@W2^T + b2 (84 items) ----
            if (bid < 84) mlp2_item(sm.g, bid, W2, b2);
            gsync();
        }
    }

    for (int idx = bid*NTHR + tid; idx < NB*20*DD; idx += GRID*NTHR) {
        int d = idx & (DD - 1);
        int srow = idx >> 8;
        int b = srow / 20, sidx = srow - b*20;
        out_slots[idx] = g_slots[((size_t)b * NS + sidx) * DD + d];
    }
}

// ---------------- kv projection GEMM: 128x128 tiles (measured 92% peak) ----
__global__ void __launch_bounds__(256)
kv_gemm(const float* __restrict__ A,
        const float* __restrict__ W,
        const float* __restrict__ bias,
        float* __restrict__ C,
        const float* __restrict__ gamma,
        const float* __restrict__ beta)
{
    __shared__ float As[32][132];
    __shared__ float Ws[32][132];
    __shared__ float s_mean[128], s_rstd[128];
    __shared__ float s_red[128][2][2];

    const int tid  = threadIdx.x;
    const int row0 = blockIdx.y * 128;
    const int col0 = blockIdx.x * 128;

    {
        int r = tid >> 1, p = tid & 1;
        const float4* ap = reinterpret_cast<const float4*>(A + (size_t)(row0 + r) * DD + p * 128);
        float s = 0.f, s2 = 0.f;
        #pragma unroll
        for (int u = 0; u < 32; ++u) {
            float4 x = ap[u];
            s  += x.x + x.y + x.z + x.w;
            s2 += x.x*x.x + x.y*x.y + x.z*x.z + x.w*x.w;
        }
        s_red[r][p][0] = s; s_red[r][p][1] = s2;
        __syncthreads();
        if (tid < 128) {
            float ss  = s_red[tid][0][0] + s_red[tid][1][0];
            float ss2 = s_red[tid][0][1] + s_red[tid][1][1];
            float m = ss * (1.0f/DD);
            s_mean[tid] = m;
            s_rstd[tid] = rsqrtf(ss2*(1.0f/DD) - m*m + LN_EPS);
        }
        __syncthreads();
    }

    float acc[8][8] = {};
    const int ty = tid >> 4;
    const int tx = tid & 15;

    for (int kk = 0; kk < DD; kk += 32) {
        #pragma unroll
        for (int l = 0; l < 4; ++l) {
            int t = tid + l * 256;
            int i = t >> 3, kq = (t & 7) << 2;
            float4 v = *reinterpret_cast<const float4*>(A + (size_t)(row0 + i) * DD + kk + kq);
            float m = s_mean[i], rs = s_rstd[i];
            float4 g  = *reinterpret_cast<const float4*>(gamma + kk + kq);
            float4 bb = *reinterpret_cast<const float4*>(beta  + kk + kq);
            v.x = (v.x - m)*rs*g.x + bb.x;
            v.y = (v.y - m)*rs*g.y + bb.y;
            v.z = (v.z - m)*rs*g.z + bb.z;
            v.w = (v.w - m)*rs*g.w + bb.w;
            As[kq+0][i]=v.x; As[kq+1][i]=v.y; As[kq+2][i]=v.z; As[kq+3][i]=v.w;
        }
        #pragma unroll
        for (int l = 0; l < 4; ++l) {
            int t = tid + l * 256;
            int j = t >> 3, kq = (t & 7) << 2;
            float4 v = *reinterpret_cast<const float4*>(W + (size_t)(col0 + j) * DD + kk + kq);
            Ws[kq+0][j]=v.x; Ws[kq+1][j]=v.y; Ws[kq+2][j]=v.z; Ws[kq+3][j]=v.w;
        }
        __syncthreads();
        #pragma unroll
        for (int k = 0; k < 32; ++k) {
            float4 a0 = *reinterpret_cast<const float4*>(&As[k][ty<<2]);
            float4 a1 = *reinterpret_cast<const float4*>(&As[k][64 + (ty<<2)]);
            float4 b0 = *reinterpret_cast<const float4*>(&Ws[k][tx<<2]);
            float4 b1 = *reinterpret_cast<const float4*>(&Ws[k][64 + (tx<<2)]);
            float av[8] = {a0.x,a0.y,a0.z,a0.w, a1.x,a1.y,a1.z,a1.w};
            float bv[8] = {b0.x,b0.y,b0.z,b0.w, b1.x,b1.y,b1.z,b1.w};
            #pragma unroll
            for (int i = 0; i < 8; ++i)
                #pragma unroll
                for (int j = 0; j < 8; ++j)
                    acc[i][j] += av[i] * bv[j];
        }
        __syncthreads();
    }

    float4 bb0 = *reinterpret_cast<const float4*>(bias + col0 + (tx<<2));
    float4 bb1 = *reinterpret_cast<const float4*>(bias + col0 + 64 + (tx<<2));
    #pragma unroll
    for (int ai = 0; ai < 2; ++ai) {
        #pragma unroll
        for (int ii = 0; ii < 4; ++ii) {
            int r = row0 + ai*64 + (ty<<2) + ii;
            int ix = ai*4 + ii;
            float4 o0, o1;
            o0.x = acc[ix][0] + bb0.x; o0.y = acc[ix][1] + bb0.y;
            o0.z = acc[ix][2] + bb0.z; o0.w = acc[ix][3] + bb0.w;
            o1.x = acc[ix][4] + bb1.x; o1.y = acc[ix][5] + bb1.y;
            o1.z = acc[ix][6] + bb1.z; o1.w = acc[ix][7] + bb1.w;
            *reinterpret_cast<float4*>(C + (size_t)r * DD + col0 + (tx<<2)) = o0;
            *reinterpret_cast<float4*>(C + (size_t)r * DD + col0 + 64 + (tx<<2)) = o1;
        }
    }
}

// ---------------- launch ---------------------------------------------------
extern "C" void kernel_launch(void* const* d_in, const int* in_sizes, int n_in,
                              void* d_out, int out_size)
{
    const float* inputs = (const float*)d_in[0];
    const float* noise  = (const float*)d_in[1];
    const float* mu     = (const float*)d_in[2];
    const float* sigma  = (const float*)d_in[3];
    const float* Wq = (const float*)d_in[4];   const float* bq = (const float*)d_in[5];
    const float* Wk = (const float*)d_in[6];   const float* bk = (const float*)d_in[7];
    const float* Wv = (const float*)d_in[8];   const float* bv = (const float*)d_in[9];
    const float* W1 = (const float*)d_in[10];  const float* b1 = (const float*)d_in[11];
    const float* W2 = (const float*)d_in[12];  const float* b2 = (const float*)d_in[13];
    const float* W_ih = (const float*)d_in[14]; const float* b_ih = (const float*)d_in[15];
    const float* W_hh = (const float*)d_in[16]; const float* b_hh = (const float*)d_in[17];
    const float* gin  = (const float*)d_in[18]; const float* bein = (const float*)d_in[19];
    const float* gsl  = (const float*)d_in[20]; const float* besl = (const float*)d_in[21];
    const float* gff  = (const float*)d_in[22]; const float* beff = (const float*)d_in[23];

    float* out = (float*)d_out;
    float* out_slots = out;
    float* out_attn  = out + NB * 20 * DD;

    float *pk, *pv;
    cudaGetSymbolAddress((void**)&pk, g_k);
    cudaGetSymbolAddress((void**)&pv, g_v);

    // k,v projections for all frames (LN fused), fully parallel
    {
        const int M = NB * NFR * NT;          // 98304
        dim3 grid(DD / 128, M / 128);         // (2, 768)
        kv_gemm<<<grid, 256>>>(inputs, Wk, bk, pk, gin, bein);
        kv_gemm<<<grid, 256>>>(inputs, Wv, bv, pv, gin, bein);
    }

    // entire serial chain: one persistent kernel, pipelined tiles
    persist_kernel<<<GRID, NTHR>>>(noise, mu, sigma,
                                   Wq, bq, W1, b1, W2, b2,
                                   W_ih, b_ih, W_hh, b_hh,
                                   gsl, besl, gff, beff,
                                   out_slots, out_attn);
}